// round 16
// baseline (speedup 1.0000x reference)
#include <cuda_runtime.h>
#include <cuda_fp16.h>
#include <math.h>
#include <stdint.h>

#define B_ 8
#define N_ 1024
#define C_ 768
#define H_ 12
#define D_ 64
#define M_ (B_*N_)   // 8192

// Scratch (allocation-free rule: __device__ globals), fp16 operands
__device__ __align__(16) __half g_x16[M_*C_];        // x, row-major [m][768]
__device__ __align__(16) __half g_wa16[3*C_*C_];     // w_attn^T [2304][768]
__device__ __align__(16) __half g_wp16[C_*C_];       // w_proj^T [768][768]
__device__ __align__(16) __half g_q16[B_*H_*N_*D_];  // [B,H,N,D]
__device__ __align__(16) __half g_k16[B_*H_*N_*D_];
__device__ __align__(16) __half g_v16[B_*H_*N_*D_];
__device__ __align__(16) __half g_att16[M_*C_];      // [B,N,C]

__device__ __forceinline__ uint32_t pack_h2(float x, float y) {
  __half2 h = __floats2half2_rn(x, y);
  return *reinterpret_cast<uint32_t*>(&h);
}

__device__ __forceinline__ void mma_f16(float* d, const uint32_t* a, const uint32_t* b) {
  asm volatile(
    "mma.sync.aligned.m16n8k16.row.col.f32.f16.f16.f32 "
    "{%0,%1,%2,%3}, {%4,%5,%6,%7}, {%8,%9}, {%0,%1,%2,%3};"
    : "+f"(d[0]), "+f"(d[1]), "+f"(d[2]), "+f"(d[3])
    : "r"(a[0]), "r"(a[1]), "r"(a[2]), "r"(a[3]), "r"(b[0]), "r"(b[1]));
}

__device__ __forceinline__ void ldsm4(uint32_t* r, uint32_t a) {
  asm volatile("ldmatrix.sync.aligned.m8n8.x4.shared.b16 {%0,%1,%2,%3}, [%4];"
    : "=r"(r[0]), "=r"(r[1]), "=r"(r[2]), "=r"(r[3]) : "r"(a));
}
__device__ __forceinline__ void ldsm4t(uint32_t* r, uint32_t a) {
  asm volatile("ldmatrix.sync.aligned.m8n8.x4.trans.shared.b16 {%0,%1,%2,%3}, [%4];"
    : "=r"(r[0]), "=r"(r[1]), "=r"(r[2]), "=r"(r[3]) : "r"(a));
}
__device__ __forceinline__ uint32_t smaddr(const void* p) {
  return (uint32_t)__cvta_generic_to_shared(p);
}
__device__ __forceinline__ void cp16(uint32_t dst, const void* src) {
  asm volatile("cp.async.cg.shared.global [%0], [%1], 16;" :: "r"(dst), "l"(src) : "memory");
}
#define CP_COMMIT() asm volatile("cp.async.commit_group;" ::: "memory")
template<int N> __device__ __forceinline__ void cp_wait() {
  asm volatile("cp.async.wait_group %0;" :: "n"(N) : "memory");
}

// ---------------------------------------------------------------------------
// Prep kernels
// ---------------------------------------------------------------------------
__global__ void cvt_x_kernel(const float* __restrict__ x) {
  const int i = blockIdx.x * 256 + threadIdx.x;
  const float4 v = ((const float4*)x)[i];
  uint2 o;
  o.x = pack_h2(v.x, v.y);
  o.y = pack_h2(v.z, v.w);
  ((uint2*)g_x16)[i] = o;
}

template<bool ATTN>   // src [768(k)][cols(n)] -> dst fp16 [n][k]
__global__ void transpose_h_kernel(const float* __restrict__ src, int cols) {
  __shared__ float tb[32][33];
  __half* dst = ATTN ? g_wa16 : g_wp16;
  const int cb = blockIdx.x * 32, rb = blockIdx.y * 32;
  const int x = threadIdx.x, y = threadIdx.y;
#pragma unroll
  for (int i = 0; i < 32; i += 8)
    tb[y + i][x] = src[(size_t)(rb + y + i) * cols + cb + x];
  __syncthreads();
#pragma unroll
  for (int i = 0; i < 32; i += 8)
    dst[(size_t)(cb + y + i) * 768 + rb + x] = __float2half_rn(tb[x][y + i]);
}

// ---------------------------------------------------------------------------
// fp16 GEMM, 64x64 warp tiles, K=32 stages (2 halves per barrier).
// CTA 256m x 128n, 8 warps (4m x 2n). cp.async 3-stage ring, 90KB smem.
// Pitch 40 halves (20 words): 8 consecutive rows hit 8 distinct bank
// groups -> staging and ldmatrix conflict-free.
// ---------------------------------------------------------------------------
#define GP2 40
#define A_BUF_B (256 * GP2 * 2)   // 20480 bytes per A stage
#define B_BUF_B (128 * GP2 * 2)   // 10240 bytes per B stage
template<bool QKV>
__global__ __launch_bounds__(256) void mma_gemm(
    const float* __restrict__ bias, float* __restrict__ Out)
{
  extern __shared__ __half dsm[];
  __half* Adyn = dsm;                   // 3 stages of 256*GP2
  __half* Bdyn = dsm + 3 * 256 * GP2;   // 3 stages of 128*GP2

  const int tid  = threadIdx.x;
  const int lane = tid & 31;
  const int w    = tid >> 5;
  const int wm   = w >> 1;
  const int wn   = w & 1;
  const int m0 = blockIdx.y * 256, n0 = blockIdx.x * 128;

  const __half* A16 = QKV ? g_x16 : g_att16;
  const __half* W16 = QKV ? g_wa16 : g_wp16;

  float acc[4][8][4];
#pragma unroll
  for (int i = 0; i < 4; i++)
#pragma unroll
    for (int j = 0; j < 8; j++)
#pragma unroll
      for (int q = 0; q < 4; q++) acc[i][j][q] = 0.f;

  // staging: A row = tid, 4 x 16B chunks; B row = tid&127, 2 chunks of 4.
  const int b_r = tid & 127, b_c = tid >> 7;   // b_c in {0,1}: chunks c, c+2
  const __half* aptr = A16 + (size_t)(m0 + tid) * 768;
  const __half* bptr = W16 + (size_t)(n0 + b_r) * 768;
  const uint32_t a_sm = smaddr(Adyn) + tid * GP2 * 2;
  const uint32_t b_sm = smaddr(Bdyn) + b_r * GP2 * 2;

  auto issue = [&](int kt, int buf) {      // kt indexes K=32 stages
    const int k0 = kt * 32;
#pragma unroll
    for (int c = 0; c < 4; c++)
      cp16(a_sm + buf * A_BUF_B + c * 16, aptr + k0 + c * 8);
#pragma unroll
    for (int it = 0; it < 2; it++) {
      const int c = b_c + it * 2;
      cp16(b_sm + buf * B_BUF_B + c * 16, bptr + k0 + c * 8);
    }
  };

  // ldmatrix lane addressing (buffer 0, half 0)
  const int lrow = (lane & 7) + ((lane >> 3) & 1) * 8;
  const int lkc  = (lane >> 4) * 8;
  uint32_t aAddr[4], bAddr[4];
#pragma unroll
  for (int mf = 0; mf < 4; mf++)
    aAddr[mf] = smaddr(&Adyn[(wm * 64 + mf * 16 + lrow) * GP2 + lkc]);
  const int brow = 8 * (lane >> 4) + (lane & 7);
  const int bkc  = ((lane >> 3) & 1) * 8;
#pragma unroll
  for (int p = 0; p < 4; p++)
    bAddr[p] = smaddr(&Bdyn[(wn * 64 + p * 16 + brow) * GP2 + bkc]);

  // prologue: 2 stages in flight
  issue(0, 0); CP_COMMIT();
  issue(1, 1); CP_COMMIT();

  int cur = 0;
  for (int kt = 0; kt < 24; kt++) {
    if (kt < 23) cp_wait<1>(); else cp_wait<0>();
    __syncthreads();
    if (kt + 2 < 24) {
      const int nb = (cur == 0) ? 2 : cur - 1;
      issue(kt + 2, nb);
      CP_COMMIT();
    }

    const uint32_t aOff = (uint32_t)cur * A_BUF_B;
    const uint32_t bOff = (uint32_t)cur * B_BUF_B;
#pragma unroll
    for (int hh = 0; hh < 2; hh++) {       // two K=16 halves per stage
      const uint32_t hB = hh * 32;         // 16 halves = 32 bytes
      uint32_t af[4][4];
#pragma unroll
      for (int mf = 0; mf < 4; mf++)
        ldsm4(af[mf], aAddr[mf] + aOff + hB);
#pragma unroll
      for (int p = 0; p < 4; p++) {
        uint32_t bf[4];   // {b0_e, b1_e, b0_o, b1_o}
        ldsm4(bf, bAddr[p] + bOff + hB);
#pragma unroll
        for (int mf = 0; mf < 4; mf++) {
          mma_f16(acc[mf][2 * p + 0], af[mf], bf + 0);
          mma_f16(acc[mf][2 * p + 1], af[mf], bf + 2);
        }
      }
    }
    cur = (cur == 2) ? 0 : cur + 1;
  }

  // --- epilogue ---
  const int g = lane >> 2, tq = lane & 3;
#pragma unroll
  for (int mf = 0; mf < 4; mf++) {
    const int r0 = m0 + wm * 64 + mf * 16 + g;
#pragma unroll
    for (int nf = 0; nf < 8; nf++) {
      const int col = n0 + wn * 64 + nf * 8 + tq * 2;
      const float bx = bias[col], by = bias[col + 1];
#pragma unroll
      for (int half_ = 0; half_ < 2; half_++) {
        const int r = r0 + half_ * 8;
        const float ox = acc[mf][nf][half_ * 2 + 0] + bx;
        const float oy = acc[mf][nf][half_ * 2 + 1] + by;
        if (QKV) {
          const int bb = r >> 10, t = r & 1023;
          const int which = col / 768;
          const int c = col - which * 768;
          const int hh = c >> 6, d = c & 63;
          __half* dst = (which == 0) ? g_q16 : (which == 1) ? g_k16 : g_v16;
          const size_t idx = ((size_t)((bb * 12 + hh) * 1024 + t)) * 64 + d;
          ((uint32_t*)dst)[idx >> 1] = pack_h2(ox, oy);
        } else {
          float2 o; o.x = ox; o.y = oy;
          *(float2*)&Out[(size_t)r * 768 + col] = o;
        }
      }
    }
  }
}

// ---------------------------------------------------------------------------
// fp16 flash attention, cp.async double-buffered K/V (unchanged from R15).
// ---------------------------------------------------------------------------
#define AP 72
#define KV_BUF_B (64 * AP * 2)   // 9216 bytes per K (or V) stage
__global__ __launch_bounds__(256) void attn_mma(const int* __restrict__ pad_mask)
{
  extern __shared__ __half dsm[];
  __half* sQ = dsm;
  __half* sK = dsm + 128 * AP;
  __half* sV = dsm + 128 * AP + 2 * 64 * AP;

  const int tid  = threadIdx.x;
  const int lane = tid & 31;
  const int w    = tid >> 5;
  const int g    = lane >> 2;
  const int t    = lane & 3;
  const int bh = blockIdx.y;
  const int b  = bh / 12, h = bh % 12;
  const int q0 = blockIdx.x << 7;

  const __half* Qg = g_q16 + (size_t)bh * (N_*D_) + (size_t)q0 * D_;
  const __half* Kg = g_k16 + (size_t)bh * (N_*D_);
  const __half* Vg = g_v16 + (size_t)bh * (N_*D_);

  int kv_soff[2], kv_goff[2];
#pragma unroll
  for (int it = 0; it < 2; it++) {
    const int idx = tid + it * 256;
    const int r = idx >> 3, d8 = idx & 7;
    kv_soff[it] = (r * AP + d8 * 8) * 2;
    kv_goff[it] = r * 64 + d8 * 8;
  }
  const uint32_t k_sm = smaddr(sK);
  const uint32_t v_sm = smaddr(sV);
  auto issueKV = [&](int kt, int buf) {
#pragma unroll
    for (int it = 0; it < 2; it++) {
      cp16(k_sm + buf * KV_BUF_B + kv_soff[it], Kg + (size_t)kt * 64 * 64 + kv_goff[it]);
      cp16(v_sm + buf * KV_BUF_B + kv_soff[it], Vg + (size_t)kt * 64 * 64 + kv_goff[it]);
    }
  };

  issueKV(0, 0); CP_COMMIT();
#pragma unroll
  for (int it = 0; it < 4; it++) {
    const int idx = tid + it * 256;
    const int r = idx >> 3, d8 = idx & 7;
    *(uint4*)&sQ[r * AP + d8 * 8] = *(const uint4*)(Qg + (size_t)r * 64 + d8 * 8);
  }
  __syncthreads();

  const int lrow = (lane & 7) + ((lane >> 3) & 1) * 8;
  const uint32_t qAddr = smaddr(&sQ[(w * 16 + lrow) * AP + (lane >> 4) * 8]);
  uint32_t aQ[4][4];
#pragma unroll
  for (int kc = 0; kc < 4; kc++)
    ldsm4(aQ[kc], qAddr + kc * 32);

  const int brow = 8 * (lane >> 4) + (lane & 7);
  const int bkc  = ((lane >> 3) & 1) * 8;
  uint32_t kAddr[4], vAddr[4];
#pragma unroll
  for (int p = 0; p < 4; p++) {
    kAddr[p] = smaddr(&sK[(p * 16 + brow) * AP + bkc]);
    vAddr[p] = smaddr(&sV[(8 * ((lane >> 3) & 1) + (lane & 7)) * AP + p * 16 + (lane >> 4) * 8]);
  }
  __half* Pw = &sQ[w * 16 * AP];
  const uint32_t pAddr = smaddr(&Pw[lrow * AP + (lane >> 4) * 8]);

  const bool mz0 = (pad_mask[b * N_ + q0 + w * 16 + g] == 0);
  const bool mz1 = (pad_mask[b * N_ + q0 + w * 16 + g + 8] == 0);

  float accO[8][4];
#pragma unroll
  for (int nf = 0; nf < 8; nf++)
#pragma unroll
    for (int j = 0; j < 4; j++) accO[nf][j] = 0.f;
  float rowM0 = -INFINITY, rowM1 = -INFINITY, rowL0 = 0.f, rowL1 = 0.f;

  for (int kt = 0; kt < 16; kt++) {
    cp_wait<0>();
    __syncthreads();
    if (kt + 1 < 16) { issueKV(kt + 1, (kt + 1) & 1); CP_COMMIT(); }
    const uint32_t kvOff = (uint32_t)(kt & 1) * KV_BUF_B;

    float accS[8][4];
#pragma unroll
    for (int nf = 0; nf < 8; nf++)
#pragma unroll
      for (int j = 0; j < 4; j++) accS[nf][j] = 0.f;
#pragma unroll
    for (int kc = 0; kc < 4; kc++) {
#pragma unroll
      for (int p = 0; p < 4; p++) {
        uint32_t bf[4];
        ldsm4(bf, kAddr[p] + kvOff + kc * 32);
        mma_f16(accS[2 * p + 0], aQ[kc], bf + 0);
        mma_f16(accS[2 * p + 1], aQ[kc], bf + 2);
      }
    }

    float mx0 = -INFINITY, mx1 = -INFINITY;
#pragma unroll
    for (int nf = 0; nf < 8; nf++) {
      accS[nf][0] = mz0 ? -INFINITY : accS[nf][0] * 0.125f;
      accS[nf][1] = mz0 ? -INFINITY : accS[nf][1] * 0.125f;
      accS[nf][2] = mz1 ? -INFINITY : accS[nf][2] * 0.125f;
      accS[nf][3] = mz1 ? -INFINITY : accS[nf][3] * 0.125f;
      mx0 = fmaxf(mx0, fmaxf(accS[nf][0], accS[nf][1]));
      mx1 = fmaxf(mx1, fmaxf(accS[nf][2], accS[nf][3]));
    }
#pragma unroll
    for (int o = 1; o <= 2; o <<= 1) {
      mx0 = fmaxf(mx0, __shfl_xor_sync(0xffffffffu, mx0, o));
      mx1 = fmaxf(mx1, __shfl_xor_sync(0xffffffffu, mx1, o));
    }
    const float mn0 = fmaxf(rowM0, mx0), mn1 = fmaxf(rowM1, mx1);
    const float fac0 = __expf(rowM0 - mn0), fac1 = __expf(rowM1 - mn1);
    rowM0 = mn0; rowM1 = mn1;
    float sum0 = 0.f, sum1 = 0.f;
#pragma unroll
    for (int nf = 0; nf < 8; nf++) {
      accS[nf][0] = __expf(accS[nf][0] - mn0);
      accS[nf][1] = __expf(accS[nf][1] - mn0);
      accS[nf][2] = __expf(accS[nf][2] - mn1);
      accS[nf][3] = __expf(accS[nf][3] - mn1);
      sum0 += accS[nf][0] + accS[nf][1];
      sum1 += accS[nf][2] + accS[nf][3];
    }
#pragma unroll
    for (int o = 1; o <= 2; o <<= 1) {
      sum0 += __shfl_xor_sync(0xffffffffu, sum0, o);
      sum1 += __shfl_xor_sync(0xffffffffu, sum1, o);
    }
    rowL0 = rowL0 * fac0 + sum0;
    rowL1 = rowL1 * fac1 + sum1;
#pragma unroll
    for (int nf = 0; nf < 8; nf++) {
      accO[nf][0] *= fac0; accO[nf][1] *= fac0;
      accO[nf][2] *= fac1; accO[nf][3] *= fac1;
    }

#pragma unroll
    for (int nf = 0; nf < 8; nf++) {
      *(uint32_t*)&Pw[g * AP + nf * 8 + 2 * t]       = pack_h2(accS[nf][0], accS[nf][1]);
      *(uint32_t*)&Pw[(g + 8) * AP + nf * 8 + 2 * t] = pack_h2(accS[nf][2], accS[nf][3]);
    }
    __syncwarp();

#pragma unroll
    for (int kcP = 0; kcP < 4; kcP++) {
      uint32_t aP[4];
      ldsm4(aP, pAddr + kcP * 32);
#pragma unroll
      for (int p = 0; p < 4; p++) {
        uint32_t bf[4];
        ldsm4t(bf, vAddr[p] + kvOff + kcP * (16 * AP * 2));
        mma_f16(accO[2 * p + 0], aP, bf + 0);
        mma_f16(accO[2 * p + 1], aP, bf + 2);
      }
    }
    __syncwarp();
  }

  const float inv0 = 1.f / rowL0, inv1 = 1.f / rowL1;
  const int row0 = q0 + w * 16 + g;
#pragma unroll
  for (int nf = 0; nf < 8; nf++) {
    const int col = h * 64 + nf * 8 + t * 2;
    const size_t i0 = (size_t)(b * N_ + row0) * C_ + col;
    const size_t i1 = (size_t)(b * N_ + row0 + 8) * C_ + col;
    ((uint32_t*)g_att16)[i0 >> 1] = pack_h2(accO[nf][0] * inv0, accO[nf][1] * inv0);
    ((uint32_t*)g_att16)[i1 >> 1] = pack_h2(accO[nf][2] * inv1, accO[nf][3] * inv1);
  }
}

extern "C" void kernel_launch(void* const* d_in, const int* in_sizes, int n_in,
                              void* d_out, int out_size) {
  const float* x      = (const float*)d_in[0];
  const int*   pad    = (const int*)  d_in[1];
  const float* w_attn = (const float*)d_in[2];
  const float* b_attn = (const float*)d_in[3];
  const float* w_proj = (const float*)d_in[4];
  const float* b_proj = (const float*)d_in[5];
  float* out = (float*)d_out;

  const int gemm_smem = 3 * (A_BUF_B + B_BUF_B);              // 92160 B
  const int attn_smem = (128 * AP + 4 * 64 * AP) * 2;         // 55296 B
  cudaFuncSetAttribute(mma_gemm<true>,  cudaFuncAttributeMaxDynamicSharedMemorySize, gemm_smem);
  cudaFuncSetAttribute(mma_gemm<false>, cudaFuncAttributeMaxDynamicSharedMemorySize, gemm_smem);
  cudaFuncSetAttribute(attn_mma, cudaFuncAttributeMaxDynamicSharedMemorySize, attn_smem);

  // 0) prep: fp16 conversions / weight transposes
  cvt_x_kernel<<<(M_*C_/4 + 255) / 256, 256>>>(x);
  transpose_h_kernel<true> <<<dim3(2304/32, 768/32), dim3(32, 8)>>>(w_attn, 2304);
  transpose_h_kernel<false><<<dim3(768/32,  768/32), dim3(32, 8)>>>(w_proj, 768);
  // 1) QKV projection -> fp16 [B,H,N,D]  (CTA tile 256x128)
  mma_gemm<true><<<dim3(18, 32), 256, gemm_smem>>>(b_attn, nullptr);
  // 2) fused attention -> fp16 [B,N,C]
  attn_mma<<<dim3(8, 96), 256, attn_smem>>>(pad);
  // 3) output projection -> fp32 d_out
  mma_gemm<false><<<dim3(6, 32), 256, gemm_smem>>>(b_proj, out);
}

// round 17
// speedup vs baseline: 1.2722x; 1.2722x over previous
#include <cuda_runtime.h>
#include <cuda_fp16.h>
#include <math.h>
#include <stdint.h>

#define B_ 8
#define N_ 1024
#define C_ 768
#define H_ 12
#define D_ 64
#define M_ (B_*N_)   // 8192

// Scratch (allocation-free rule: __device__ globals), fp16 operands
__device__ __align__(16) __half g_x16[M_*C_];        // x, row-major [m][768]
__device__ __align__(16) __half g_wa16[3*C_*C_];     // w_attn^T [2304][768]
__device__ __align__(16) __half g_wp16[C_*C_];       // w_proj^T [768][768]
__device__ __align__(16) __half g_q16[B_*H_*N_*D_];  // [B,H,N,D]
__device__ __align__(16) __half g_k16[B_*H_*N_*D_];
__device__ __align__(16) __half g_v16[B_*H_*N_*D_];
__device__ __align__(16) __half g_att16[M_*C_];      // [B,N,C]

__device__ __forceinline__ uint32_t pack_h2(float x, float y) {
  __half2 h = __floats2half2_rn(x, y);
  return *reinterpret_cast<uint32_t*>(&h);
}

__device__ __forceinline__ void mma_f16(float* d, const uint32_t* a, const uint32_t* b) {
  asm volatile(
    "mma.sync.aligned.m16n8k16.row.col.f32.f16.f16.f32 "
    "{%0,%1,%2,%3}, {%4,%5,%6,%7}, {%8,%9}, {%0,%1,%2,%3};"
    : "+f"(d[0]), "+f"(d[1]), "+f"(d[2]), "+f"(d[3])
    : "r"(a[0]), "r"(a[1]), "r"(a[2]), "r"(a[3]), "r"(b[0]), "r"(b[1]));
}

__device__ __forceinline__ void ldsm4(uint32_t* r, uint32_t a) {
  asm volatile("ldmatrix.sync.aligned.m8n8.x4.shared.b16 {%0,%1,%2,%3}, [%4];"
    : "=r"(r[0]), "=r"(r[1]), "=r"(r[2]), "=r"(r[3]) : "r"(a));
}
__device__ __forceinline__ void ldsm4t(uint32_t* r, uint32_t a) {
  asm volatile("ldmatrix.sync.aligned.m8n8.x4.trans.shared.b16 {%0,%1,%2,%3}, [%4];"
    : "=r"(r[0]), "=r"(r[1]), "=r"(r[2]), "=r"(r[3]) : "r"(a));
}
__device__ __forceinline__ uint32_t smaddr(const void* p) {
  return (uint32_t)__cvta_generic_to_shared(p);
}
__device__ __forceinline__ void cp16(uint32_t dst, const void* src) {
  asm volatile("cp.async.cg.shared.global [%0], [%1], 16;" :: "r"(dst), "l"(src) : "memory");
}
#define CP_COMMIT() asm volatile("cp.async.commit_group;" ::: "memory")
template<int N> __device__ __forceinline__ void cp_wait() {
  asm volatile("cp.async.wait_group %0;" :: "n"(N) : "memory");
}

// ---------------------------------------------------------------------------
// Prep kernels
// ---------------------------------------------------------------------------
__global__ void cvt_x_kernel(const float* __restrict__ x) {
  const int i = blockIdx.x * 256 + threadIdx.x;
  const float4 v = ((const float4*)x)[i];
  uint2 o;
  o.x = pack_h2(v.x, v.y);
  o.y = pack_h2(v.z, v.w);
  ((uint2*)g_x16)[i] = o;
}

template<bool ATTN>   // src [768(k)][cols(n)] -> dst fp16 [n][k]
__global__ void transpose_h_kernel(const float* __restrict__ src, int cols) {
  __shared__ float tb[32][33];
  __half* dst = ATTN ? g_wa16 : g_wp16;
  const int cb = blockIdx.x * 32, rb = blockIdx.y * 32;
  const int x = threadIdx.x, y = threadIdx.y;
#pragma unroll
  for (int i = 0; i < 32; i += 8)
    tb[y + i][x] = src[(size_t)(rb + y + i) * cols + cb + x];
  __syncthreads();
#pragma unroll
  for (int i = 0; i < 32; i += 8)
    dst[(size_t)(cb + y + i) * 768 + rb + x] = __float2half_rn(tb[x][y + i]);
}

// ---------------------------------------------------------------------------
// fp16 GEMM, 64x32 warp tiles, 2 CTAs/SM (occupancy over reuse).
// CTA 128m x 128n, 8 warps (2m x 4n), K=32 stages, cp.async 3-stage ring.
// Smem 60KB/CTA -> 2 CTAs fit the 228KB carveout; regs capped 128 (natural
// ~110 with acc=64 -> no spill).
// Pitch 40 halves: 8 consecutive rows hit 8 distinct 16B bank quads.
// ---------------------------------------------------------------------------
#define GP2 40
#define A_BUF_B (128 * GP2 * 2)   // 10240 bytes per A stage
#define B_BUF_B (128 * GP2 * 2)   // 10240 bytes per B stage
template<bool QKV>
__global__ __launch_bounds__(256, 2) void mma_gemm(
    const float* __restrict__ bias, float* __restrict__ Out)
{
  extern __shared__ __half dsm[];
  __half* Adyn = dsm;                   // 3 stages of 128*GP2
  __half* Bdyn = dsm + 3 * 128 * GP2;   // 3 stages of 128*GP2

  const int tid  = threadIdx.x;
  const int lane = tid & 31;
  const int w    = tid >> 5;
  const int wm   = w >> 2;            // 0..1  (64-row stripe)
  const int wn   = w & 3;             // 0..3  (32-col stripe)
  const int m0 = blockIdx.y * 128, n0 = blockIdx.x * 128;

  const __half* A16 = QKV ? g_x16 : g_att16;
  const __half* W16 = QKV ? g_wa16 : g_wp16;

  float acc[4][4][4];                 // [mf][nf][reg] = 64 regs
#pragma unroll
  for (int i = 0; i < 4; i++)
#pragma unroll
    for (int j = 0; j < 4; j++)
#pragma unroll
      for (int q = 0; q < 4; q++) acc[i][j][q] = 0.f;

  // staging: idx = tid + it*256, it<2: r = idx>>2 (0..127), c = idx&3 (16B chunk)
  int s_soff[2];
  const __half* aptr;
  const __half* bptr;
  {
    // per-thread global base for chunk 0 of its row; chunk selected per it
  }
  int s_r[2], s_c[2];
#pragma unroll
  for (int it = 0; it < 2; it++) {
    const int idx = tid + it * 256;
    s_r[it] = idx >> 2;
    s_c[it] = idx & 3;
    s_soff[it] = (s_r[it] * GP2 + s_c[it] * 8) * 2;   // bytes
  }
  aptr = A16 + (size_t)m0 * 768;
  bptr = W16 + (size_t)n0 * 768;
  const uint32_t a_sm = smaddr(Adyn);
  const uint32_t b_sm = smaddr(Bdyn);

  auto issue = [&](int kt, int buf) {      // kt indexes K=32 stages
    const int k0 = kt * 32;
#pragma unroll
    for (int it = 0; it < 2; it++) {
      cp16(a_sm + buf * A_BUF_B + s_soff[it], aptr + (size_t)s_r[it] * 768 + k0 + s_c[it] * 8);
      cp16(b_sm + buf * B_BUF_B + s_soff[it], bptr + (size_t)s_r[it] * 768 + k0 + s_c[it] * 8);
    }
  };

  // ldmatrix lane addressing (buffer 0, half 0)
  const int lrow = (lane & 7) + ((lane >> 3) & 1) * 8;
  const int lkc  = (lane >> 4) * 8;
  uint32_t aAddr[4], bAddr[2];
#pragma unroll
  for (int mf = 0; mf < 4; mf++)
    aAddr[mf] = smaddr(&Adyn[(wm * 64 + mf * 16 + lrow) * GP2 + lkc]);
  const int brow = 8 * (lane >> 4) + (lane & 7);
  const int bkc  = ((lane >> 3) & 1) * 8;
#pragma unroll
  for (int p = 0; p < 2; p++)
    bAddr[p] = smaddr(&Bdyn[(wn * 32 + p * 16 + brow) * GP2 + bkc]);

  // prologue: 2 stages in flight
  issue(0, 0); CP_COMMIT();
  issue(1, 1); CP_COMMIT();

  int cur = 0;
  for (int kt = 0; kt < 24; kt++) {
    if (kt < 23) cp_wait<1>(); else cp_wait<0>();
    __syncthreads();
    if (kt + 2 < 24) {
      const int nb = (cur == 0) ? 2 : cur - 1;
      issue(kt + 2, nb);
      CP_COMMIT();
    }

    const uint32_t aOff = (uint32_t)cur * A_BUF_B;
    const uint32_t bOff = (uint32_t)cur * B_BUF_B;
#pragma unroll
    for (int hh = 0; hh < 2; hh++) {       // two K=16 halves per stage
      const uint32_t hB = hh * 32;         // 16 halves = 32 bytes
      uint32_t af[4][4];
#pragma unroll
      for (int mf = 0; mf < 4; mf++)
        ldsm4(af[mf], aAddr[mf] + aOff + hB);
#pragma unroll
      for (int p = 0; p < 2; p++) {
        uint32_t bf[4];   // {b0_e, b1_e, b0_o, b1_o}
        ldsm4(bf, bAddr[p] + bOff + hB);
#pragma unroll
        for (int mf = 0; mf < 4; mf++) {
          mma_f16(acc[mf][2 * p + 0], af[mf], bf + 0);
          mma_f16(acc[mf][2 * p + 1], af[mf], bf + 2);
        }
      }
    }
    cur = (cur == 2) ? 0 : cur + 1;
  }

  // --- epilogue ---
  const int g = lane >> 2, tq = lane & 3;
#pragma unroll
  for (int mf = 0; mf < 4; mf++) {
    const int r0 = m0 + wm * 64 + mf * 16 + g;
#pragma unroll
    for (int nf = 0; nf < 4; nf++) {
      const int col = n0 + wn * 32 + nf * 8 + tq * 2;
      const float bx = bias[col], by = bias[col + 1];
#pragma unroll
      for (int half_ = 0; half_ < 2; half_++) {
        const int r = r0 + half_ * 8;
        const float ox = acc[mf][nf][half_ * 2 + 0] + bx;
        const float oy = acc[mf][nf][half_ * 2 + 1] + by;
        if (QKV) {
          const int bb = r >> 10, t = r & 1023;
          const int which = col / 768;
          const int c = col - which * 768;
          const int hh = c >> 6, d = c & 63;
          __half* dst = (which == 0) ? g_q16 : (which == 1) ? g_k16 : g_v16;
          const size_t idx = ((size_t)((bb * 12 + hh) * 1024 + t)) * 64 + d;
          ((uint32_t*)dst)[idx >> 1] = pack_h2(ox, oy);
        } else {
          float2 o; o.x = ox; o.y = oy;
          *(float2*)&Out[(size_t)r * 768 + col] = o;
        }
      }
    }
  }
}

// ---------------------------------------------------------------------------
// fp16 flash attention, cp.async double-buffered K/V (unchanged — proven).
// ---------------------------------------------------------------------------
#define AP 72
#define KV_BUF_B (64 * AP * 2)   // 9216 bytes per K (or V) stage
__global__ __launch_bounds__(256) void attn_mma(const int* __restrict__ pad_mask)
{
  extern __shared__ __half dsm[];
  __half* sQ = dsm;
  __half* sK = dsm + 128 * AP;
  __half* sV = dsm + 128 * AP + 2 * 64 * AP;

  const int tid  = threadIdx.x;
  const int lane = tid & 31;
  const int w    = tid >> 5;
  const int g    = lane >> 2;
  const int t    = lane & 3;
  const int bh = blockIdx.y;
  const int b  = bh / 12, h = bh % 12;
  const int q0 = blockIdx.x << 7;

  const __half* Qg = g_q16 + (size_t)bh * (N_*D_) + (size_t)q0 * D_;
  const __half* Kg = g_k16 + (size_t)bh * (N_*D_);
  const __half* Vg = g_v16 + (size_t)bh * (N_*D_);

  int kv_soff[2], kv_goff[2];
#pragma unroll
  for (int it = 0; it < 2; it++) {
    const int idx = tid + it * 256;
    const int r = idx >> 3, d8 = idx & 7;
    kv_soff[it] = (r * AP + d8 * 8) * 2;
    kv_goff[it] = r * 64 + d8 * 8;
  }
  const uint32_t k_sm = smaddr(sK);
  const uint32_t v_sm = smaddr(sV);
  auto issueKV = [&](int kt, int buf) {
#pragma unroll
    for (int it = 0; it < 2; it++) {
      cp16(k_sm + buf * KV_BUF_B + kv_soff[it], Kg + (size_t)kt * 64 * 64 + kv_goff[it]);
      cp16(v_sm + buf * KV_BUF_B + kv_soff[it], Vg + (size_t)kt * 64 * 64 + kv_goff[it]);
    }
  };

  issueKV(0, 0); CP_COMMIT();
#pragma unroll
  for (int it = 0; it < 4; it++) {
    const int idx = tid + it * 256;
    const int r = idx >> 3, d8 = idx & 7;
    *(uint4*)&sQ[r * AP + d8 * 8] = *(const uint4*)(Qg + (size_t)r * 64 + d8 * 8);
  }
  __syncthreads();

  const int lrow = (lane & 7) + ((lane >> 3) & 1) * 8;
  const uint32_t qAddr = smaddr(&sQ[(w * 16 + lrow) * AP + (lane >> 4) * 8]);
  uint32_t aQ[4][4];
#pragma unroll
  for (int kc = 0; kc < 4; kc++)
    ldsm4(aQ[kc], qAddr + kc * 32);

  const int brow = 8 * (lane >> 4) + (lane & 7);
  const int bkc  = ((lane >> 3) & 1) * 8;
  uint32_t kAddr[4], vAddr[4];
#pragma unroll
  for (int p = 0; p < 4; p++) {
    kAddr[p] = smaddr(&sK[(p * 16 + brow) * AP + bkc]);
    vAddr[p] = smaddr(&sV[(8 * ((lane >> 3) & 1) + (lane & 7)) * AP + p * 16 + (lane >> 4) * 8]);
  }
  __half* Pw = &sQ[w * 16 * AP];
  const uint32_t pAddr = smaddr(&Pw[lrow * AP + (lane >> 4) * 8]);

  const bool mz0 = (pad_mask[b * N_ + q0 + w * 16 + g] == 0);
  const bool mz1 = (pad_mask[b * N_ + q0 + w * 16 + g + 8] == 0);

  float accO[8][4];
#pragma unroll
  for (int nf = 0; nf < 8; nf++)
#pragma unroll
    for (int j = 0; j < 4; j++) accO[nf][j] = 0.f;
  float rowM0 = -INFINITY, rowM1 = -INFINITY, rowL0 = 0.f, rowL1 = 0.f;

  for (int kt = 0; kt < 16; kt++) {
    cp_wait<0>();
    __syncthreads();
    if (kt + 1 < 16) { issueKV(kt + 1, (kt + 1) & 1); CP_COMMIT(); }
    const uint32_t kvOff = (uint32_t)(kt & 1) * KV_BUF_B;

    float accS[8][4];
#pragma unroll
    for (int nf = 0; nf < 8; nf++)
#pragma unroll
      for (int j = 0; j < 4; j++) accS[nf][j] = 0.f;
#pragma unroll
    for (int kc = 0; kc < 4; kc++) {
#pragma unroll
      for (int p = 0; p < 4; p++) {
        uint32_t bf[4];
        ldsm4(bf, kAddr[p] + kvOff + kc * 32);
        mma_f16(accS[2 * p + 0], aQ[kc], bf + 0);
        mma_f16(accS[2 * p + 1], aQ[kc], bf + 2);
      }
    }

    float mx0 = -INFINITY, mx1 = -INFINITY;
#pragma unroll
    for (int nf = 0; nf < 8; nf++) {
      accS[nf][0] = mz0 ? -INFINITY : accS[nf][0] * 0.125f;
      accS[nf][1] = mz0 ? -INFINITY : accS[nf][1] * 0.125f;
      accS[nf][2] = mz1 ? -INFINITY : accS[nf][2] * 0.125f;
      accS[nf][3] = mz1 ? -INFINITY : accS[nf][3] * 0.125f;
      mx0 = fmaxf(mx0, fmaxf(accS[nf][0], accS[nf][1]));
      mx1 = fmaxf(mx1, fmaxf(accS[nf][2], accS[nf][3]));
    }
#pragma unroll
    for (int o = 1; o <= 2; o <<= 1) {
      mx0 = fmaxf(mx0, __shfl_xor_sync(0xffffffffu, mx0, o));
      mx1 = fmaxf(mx1, __shfl_xor_sync(0xffffffffu, mx1, o));
    }
    const float mn0 = fmaxf(rowM0, mx0), mn1 = fmaxf(rowM1, mx1);
    const float fac0 = __expf(rowM0 - mn0), fac1 = __expf(rowM1 - mn1);
    rowM0 = mn0; rowM1 = mn1;
    float sum0 = 0.f, sum1 = 0.f;
#pragma unroll
    for (int nf = 0; nf < 8; nf++) {
      accS[nf][0] = __expf(accS[nf][0] - mn0);
      accS[nf][1] = __expf(accS[nf][1] - mn0);
      accS[nf][2] = __expf(accS[nf][2] - mn1);
      accS[nf][3] = __expf(accS[nf][3] - mn1);
      sum0 += accS[nf][0] + accS[nf][1];
      sum1 += accS[nf][2] + accS[nf][3];
    }
#pragma unroll
    for (int o = 1; o <= 2; o <<= 1) {
      sum0 += __shfl_xor_sync(0xffffffffu, sum0, o);
      sum1 += __shfl_xor_sync(0xffffffffu, sum1, o);
    }
    rowL0 = rowL0 * fac0 + sum0;
    rowL1 = rowL1 * fac1 + sum1;
#pragma unroll
    for (int nf = 0; nf < 8; nf++) {
      accO[nf][0] *= fac0; accO[nf][1] *= fac0;
      accO[nf][2] *= fac1; accO[nf][3] *= fac1;
    }

#pragma unroll
    for (int nf = 0; nf < 8; nf++) {
      *(uint32_t*)&Pw[g * AP + nf * 8 + 2 * t]       = pack_h2(accS[nf][0], accS[nf][1]);
      *(uint32_t*)&Pw[(g + 8) * AP + nf * 8 + 2 * t] = pack_h2(accS[nf][2], accS[nf][3]);
    }
    __syncwarp();

#pragma unroll
    for (int kcP = 0; kcP < 4; kcP++) {
      uint32_t aP[4];
      ldsm4(aP, pAddr + kcP * 32);
#pragma unroll
      for (int p = 0; p < 4; p++) {
        uint32_t bf[4];
        ldsm4t(bf, vAddr[p] + kvOff + kcP * (16 * AP * 2));
        mma_f16(accO[2 * p + 0], aP, bf + 0);
        mma_f16(accO[2 * p + 1], aP, bf + 2);
      }
    }
    __syncwarp();
  }

  const float inv0 = 1.f / rowL0, inv1 = 1.f / rowL1;
  const int row0 = q0 + w * 16 + g;
#pragma unroll
  for (int nf = 0; nf < 8; nf++) {
    const int col = h * 64 + nf * 8 + t * 2;
    const size_t i0 = (size_t)(b * N_ + row0) * C_ + col;
    const size_t i1 = (size_t)(b * N_ + row0 + 8) * C_ + col;
    ((uint32_t*)g_att16)[i0 >> 1] = pack_h2(accO[nf][0] * inv0, accO[nf][1] * inv0);
    ((uint32_t*)g_att16)[i1 >> 1] = pack_h2(accO[nf][2] * inv1, accO[nf][3] * inv1);
  }
}

extern "C" void kernel_launch(void* const* d_in, const int* in_sizes, int n_in,
                              void* d_out, int out_size) {
  const float* x      = (const float*)d_in[0];
  const int*   pad    = (const int*)  d_in[1];
  const float* w_attn = (const float*)d_in[2];
  const float* b_attn = (const float*)d_in[3];
  const float* w_proj = (const float*)d_in[4];
  const float* b_proj = (const float*)d_in[5];
  float* out = (float*)d_out;

  const int gemm_smem = 3 * (A_BUF_B + B_BUF_B);              // 61440 B
  const int attn_smem = (128 * AP + 4 * 64 * AP) * 2;         // 55296 B
  cudaFuncSetAttribute(mma_gemm<true>,  cudaFuncAttributeMaxDynamicSharedMemorySize, gemm_smem);
  cudaFuncSetAttribute(mma_gemm<false>, cudaFuncAttributeMaxDynamicSharedMemorySize, gemm_smem);
  cudaFuncSetAttribute(attn_mma, cudaFuncAttributeMaxDynamicSharedMemorySize, attn_smem);

  // 0) prep: fp16 conversions / weight transposes
  cvt_x_kernel<<<(M_*C_/4 + 255) / 256, 256>>>(x);
  transpose_h_kernel<true> <<<dim3(2304/32, 768/32), dim3(32, 8)>>>(w_attn, 2304);
  transpose_h_kernel<false><<<dim3(768/32,  768/32), dim3(32, 8)>>>(w_proj, 768);
  // 1) QKV projection -> fp16 [B,H,N,D]  (CTA tile 128x128, 2 CTAs/SM)
  mma_gemm<true><<<dim3(18, 64), 256, gemm_smem>>>(b_attn, nullptr);
  // 2) fused attention -> fp16 [B,N,C]
  attn_mma<<<dim3(8, 96), 256, attn_smem>>>(pad);
  // 3) output projection -> fp32 d_out
  mma_gemm<false><<<dim3(6, 64), 256, gemm_smem>>>(b_proj, out);
}